// round 1
// baseline (speedup 1.0000x reference)
#include <cuda_runtime.h>
#include <math.h>

#define BDIM   4
#define NTOK   1024
#define CDIM   768
#define NH     12
#define HD     64
#define BH     (BDIM*NH)        // 48
#define MROWS  (BDIM*NTOK)      // 4096
#define THREEC (3*CDIM)         // 2304

// -------- scratch (static device memory; no allocs allowed) --------
__device__ float g_q[BH*NTOK*HD];                 // [BH, N, hd]
__device__ float g_k[BH*NTOK*HD];
__device__ float g_v[BH*NTOK*HD];
__device__ float g_attn[(size_t)BH*NTOK*NTOK];    // 201 MB: scores -> attn in place
__device__ float g_ps[BH*NTOK];                   // partial column sum(p)
__device__ float g_pp[BH*NTOK];                   // partial column sum(p*logp)
__device__ float g_mask[NTOK];
__device__ float g_ctx[MROWS*CDIM];               // (attn*mask)@v in [B,N,C]

// ============================================================
// K1: qkv = x @ qkv_w.T ; scatter into g_q/g_k/g_v [BH,N,hd]
// A = x [4096,768], B = qkv_w [2304,768]; y[m,n]=dot(A[m,:],B[n,:])
// ============================================================
__global__ void qkv_gemm(const float* __restrict__ x, const float* __restrict__ w) {
    __shared__ float As[16][65];
    __shared__ float Bs[16][65];
    const int m0 = blockIdx.y * 64;
    const int n0 = blockIdx.x * 64;
    const int tid = threadIdx.x;
    const int tx = tid & 15, ty = tid >> 4;
    float acc[4][4] = {};

    for (int k0 = 0; k0 < CDIM; k0 += 16) {
        for (int idx = tid; idx < 64 * 16; idx += 256) {
            int r = idx >> 4, c = idx & 15;
            As[c][r] = x[(m0 + r) * CDIM + k0 + c];
            Bs[c][r] = w[(n0 + r) * CDIM + k0 + c];
        }
        __syncthreads();
        #pragma unroll
        for (int kk = 0; kk < 16; kk++) {
            float a[4], b[4];
            #pragma unroll
            for (int i = 0; i < 4; i++) a[i] = As[kk][ty + 16 * i];
            #pragma unroll
            for (int j = 0; j < 4; j++) b[j] = Bs[kk][tx + 16 * j];
            #pragma unroll
            for (int i = 0; i < 4; i++)
                #pragma unroll
                for (int j = 0; j < 4; j++) acc[i][j] += a[i] * b[j];
        }
        __syncthreads();
    }
    // scatter: within a 64-wide tile, (three,h) are constant; d = tx+16j
    const int b = m0 / NTOK;
    const int three = n0 / CDIM;
    const int h = (n0 % CDIM) / HD;
    float* dst = (three == 0) ? g_q : (three == 1) ? g_k : g_v;
    const int base = ((b * NH + h) * NTOK) * HD;
    #pragma unroll
    for (int i = 0; i < 4; i++) {
        int tok = (m0 % NTOK) + ty + 16 * i;
        #pragma unroll
        for (int j = 0; j < 4; j++) {
            int d = tx + 16 * j;
            dst[base + tok * HD + d] = acc[i][j];
        }
    }
}

// ============================================================
// K2: scores[bh,q,k] = scale * dot(q[bh,q,:], k[bh,k,:])
// ============================================================
__global__ void qk_gemm() {
    __shared__ float Qs[64][65];
    __shared__ float Ks[64][65];
    const int bh = blockIdx.z;
    const int q0 = blockIdx.y * 64;
    const int k0 = blockIdx.x * 64;
    const int tid = threadIdx.x;
    const int tx = tid & 15, ty = tid >> 4;
    const float* qb = g_q + (bh * NTOK + q0) * HD;
    const float* kb = g_k + (bh * NTOK + k0) * HD;
    for (int idx = tid; idx < 64 * 64; idx += 256) {
        int r = idx >> 6, c = idx & 63;
        Qs[r][c] = qb[r * HD + c];
        Ks[r][c] = kb[r * HD + c];
    }
    __syncthreads();
    float acc[4][4] = {};
    #pragma unroll 16
    for (int d = 0; d < 64; d++) {
        float a[4], b[4];
        #pragma unroll
        for (int i = 0; i < 4; i++) a[i] = Qs[ty + 16 * i][d];
        #pragma unroll
        for (int j = 0; j < 4; j++) b[j] = Ks[tx + 16 * j][d];
        #pragma unroll
        for (int i = 0; i < 4; i++)
            #pragma unroll
            for (int j = 0; j < 4; j++) acc[i][j] += a[i] * b[j];
    }
    const float scale = 0.125f;  // hd^-0.5
    #pragma unroll
    for (int i = 0; i < 4; i++) {
        size_t row = (size_t)(bh * NTOK + q0 + ty + 16 * i) * NTOK;
        #pragma unroll
        for (int j = 0; j < 4; j++)
            g_attn[row + k0 + tx + 16 * j] = acc[i][j] * scale;
    }
}

// ============================================================
// K3: row softmax in place: p = exp(s - m - log(sum exp(s-m)))
// ============================================================
__global__ void softmax_rows() {
    const size_t row = blockIdx.x;
    float* p = g_attn + row * NTOK;
    const int tid = threadIdx.x;  // 256 threads, 4 elems each
    __shared__ float red[256];

    float v[4];
    float m = -1e30f;
    #pragma unroll
    for (int j = 0; j < 4; j++) { v[j] = p[tid + 256 * j]; m = fmaxf(m, v[j]); }
    red[tid] = m; __syncthreads();
    for (int s = 128; s > 0; s >>= 1) {
        if (tid < s) red[tid] = fmaxf(red[tid], red[tid + s]);
        __syncthreads();
    }
    m = red[0]; __syncthreads();

    float sum = 0.f;
    #pragma unroll
    for (int j = 0; j < 4; j++) { v[j] -= m; sum += expf(v[j]); }
    red[tid] = sum; __syncthreads();
    for (int s = 128; s > 0; s >>= 1) {
        if (tid < s) red[tid] += red[tid + s];
        __syncthreads();
    }
    float lse = logf(red[0]);
    #pragma unroll
    for (int j = 0; j < 4; j++) p[tid + 256 * j] = expf(v[j] - lse);
}

// ============================================================
// K4a: partial column reductions (deterministic, no atomics)
// chunk = 1024 rows; grid (4, 48); thread owns one column
// ============================================================
__global__ void col_reduce_partial() {
    const int j = blockIdx.x * 256 + threadIdx.x;   // 0..1023
    const int chunk = blockIdx.y;                   // 0..47
    const float* base = g_attn + (size_t)chunk * NTOK * NTOK + j;
    float s = 0.f, pp = 0.f;
    for (int r = 0; r < NTOK; r++) {
        float p = base[(size_t)r * NTOK];
        s += p;
        pp += (p > 0.f) ? p * logf(p) : 0.f;
    }
    g_ps[chunk * NTOK + j] = s;
    g_pp[chunk * NTOK + j] = pp;
}

// ============================================================
// K4b: finalize entropies + mask
// ============================================================
__global__ void finalize_mask(const int* __restrict__ cur_epoch_ptr) {
    const int j = blockIdx.x * 256 + threadIdx.x;   // 0..1023
    float s = 0.f, pp = 0.f;
    for (int c = 0; c < BH; c++) { s += g_ps[c * NTOK + j]; pp += g_pp[c * NTOK + j]; }
    const int ce = *cur_epoch_ptr;
    float factor = 0.f;
    for (int i = 0; i < ce; i++) factor += expf(-(float)(i + 1));
    factor *= 5.0f;
    const float thr = logf((float)CDIM) - factor;
    const float ent = logf(s) - pp / s;
    g_mask[j] = (ent <= thr) ? 1.0f : 0.0f;
}

// ============================================================
// K5: ctx[b,q,h,d] = sum_k attn[bh,q,k]*mask[k]*v[bh,k,d]
// ============================================================
__global__ void av_gemm() {
    __shared__ float Ps[64][17];
    __shared__ float Vs[16][65];
    const int bh = blockIdx.y;
    const int q0 = blockIdx.x * 64;
    const int tid = threadIdx.x;
    const int tx = tid & 15, ty = tid >> 4;
    const float* vb = g_v + bh * NTOK * HD;
    const float* pb = g_attn + (size_t)(bh * NTOK + q0) * NTOK;
    float acc[4][4] = {};

    for (int k0 = 0; k0 < NTOK; k0 += 16) {
        for (int idx = tid; idx < 64 * 16; idx += 256) {
            int r = idx >> 4, c = idx & 15;
            Ps[r][c] = pb[(size_t)r * NTOK + k0 + c] * g_mask[k0 + c];
        }
        for (int idx = tid; idx < 16 * 64; idx += 256) {
            int r = idx >> 6, c = idx & 63;
            Vs[r][c] = vb[(k0 + r) * HD + c];
        }
        __syncthreads();
        #pragma unroll
        for (int kk = 0; kk < 16; kk++) {
            float a[4], b[4];
            #pragma unroll
            for (int i = 0; i < 4; i++) a[i] = Ps[ty + 16 * i][kk];
            #pragma unroll
            for (int j = 0; j < 4; j++) b[j] = Vs[kk][tx + 16 * j];
            #pragma unroll
            for (int i = 0; i < 4; i++)
                #pragma unroll
                for (int j = 0; j < 4; j++) acc[i][j] += a[i] * b[j];
        }
        __syncthreads();
    }
    const int b = bh / NH, h = bh % NH;
    #pragma unroll
    for (int i = 0; i < 4; i++) {
        int q = q0 + ty + 16 * i;
        #pragma unroll
        for (int j = 0; j < 4; j++) {
            int d = tx + 16 * j;
            g_ctx[(b * NTOK + q) * CDIM + h * HD + d] = acc[i][j];
        }
    }
}

// ============================================================
// K6: out = ctx @ proj_w.T + proj_b
// ============================================================
__global__ void proj_gemm(const float* __restrict__ w, const float* __restrict__ bias,
                          float* __restrict__ out) {
    __shared__ float As[16][65];
    __shared__ float Bs[16][65];
    const int m0 = blockIdx.y * 64;
    const int n0 = blockIdx.x * 64;
    const int tid = threadIdx.x;
    const int tx = tid & 15, ty = tid >> 4;
    float acc[4][4] = {};

    for (int k0 = 0; k0 < CDIM; k0 += 16) {
        for (int idx = tid; idx < 64 * 16; idx += 256) {
            int r = idx >> 4, c = idx & 15;
            As[c][r] = g_ctx[(m0 + r) * CDIM + k0 + c];
            Bs[c][r] = w[(n0 + r) * CDIM + k0 + c];
        }
        __syncthreads();
        #pragma unroll
        for (int kk = 0; kk < 16; kk++) {
            float a[4], b[4];
            #pragma unroll
            for (int i = 0; i < 4; i++) a[i] = As[kk][ty + 16 * i];
            #pragma unroll
            for (int j = 0; j < 4; j++) b[j] = Bs[kk][tx + 16 * j];
            #pragma unroll
            for (int i = 0; i < 4; i++)
                #pragma unroll
                for (int j = 0; j < 4; j++) acc[i][j] += a[i] * b[j];
        }
        __syncthreads();
    }
    #pragma unroll
    for (int i = 0; i < 4; i++) {
        int m = m0 + ty + 16 * i;
        #pragma unroll
        for (int j = 0; j < 4; j++) {
            int n = n0 + tx + 16 * j;
            out[m * CDIM + n] = acc[i][j] + bias[n];
        }
    }
}

// ============================================================
extern "C" void kernel_launch(void* const* d_in, const int* in_sizes, int n_in,
                              void* d_out, int out_size) {
    const float* x      = (const float*)d_in[0];
    const float* qkv_w  = (const float*)d_in[1];
    const float* proj_w = (const float*)d_in[2];
    const float* proj_b = (const float*)d_in[3];
    const int*   ce     = (const int*)d_in[4];   // low 32 bits correct for i32/i64
    float* out = (float*)d_out;

    qkv_gemm<<<dim3(THREEC / 64, MROWS / 64), 256>>>(x, qkv_w);
    qk_gemm<<<dim3(NTOK / 64, NTOK / 64, BH), 256>>>();
    softmax_rows<<<BH * NTOK, 256>>>();
    col_reduce_partial<<<dim3(4, BH), 256>>>();
    finalize_mask<<<4, 256>>>(ce);
    av_gemm<<<dim3(NTOK / 64, BH), 256>>>();
    proj_gemm<<<dim3(CDIM / 64, MROWS / 64), 256>>>(proj_w, proj_b, out);
}